// round 11
// baseline (speedup 1.0000x reference)
#include <cuda_runtime.h>
#include <cstdint>

#define B_   4
#define C_   256
#define N_   4096

// ---------------- device scratch -------------------------------------------
// g_Qn/g_Km: [b][n][j'] j' = j ^ ((n&7)<<2)                 (32-float rows)
// g_V: [b][ch64][c][nn'] nn' = (n&63) ^ ((c&7)<<2)          (64-float rows)
__device__ float g_Qn[(size_t)B_ * N_ * 32];
__device__ float g_Km[(size_t)B_ * N_ * 32];
__device__ float g_V [(size_t)B_ * 64 * C_ * 64];

// ---------------- helpers --------------------------------------------------
__device__ __forceinline__ uint32_t smem_u32(const void* p) {
    uint32_t a;
    asm("{ .reg .u64 t; cvta.to.shared.u64 t, %1; cvt.u32.u64 %0, t; }"
        : "=r"(a) : "l"(p));
    return a;
}
__device__ __forceinline__ float f2tf(float x) {
    uint32_t r;
    asm("cvt.rna.tf32.f32 %0, %1;" : "=r"(r) : "f"(x));
    return __uint_as_float(r);
}
__device__ __forceinline__ void mma8(float4& d, const uint32_t* a, const uint32_t* b) {
    asm("mma.sync.aligned.m16n8k8.row.col.f32.tf32.tf32.f32 "
        "{%0,%1,%2,%3}, {%4,%5,%6,%7}, {%8,%9}, {%0,%1,%2,%3};"
        : "+f"(d.x), "+f"(d.y), "+f"(d.z), "+f"(d.w)
        : "r"(a[0]), "r"(a[1]), "r"(a[2]), "r"(a[3]), "r"(b[0]), "r"(b[1]));
}
#define MBAR_INIT(a, n) \
    asm volatile("mbarrier.init.shared.b64 [%0], %1;" :: "r"(a), "r"(n) : "memory")
#define MBAR_EXPECT(a, tx) \
    asm volatile("mbarrier.arrive.expect_tx.shared.b64 _, [%0], %1;" \
                 :: "r"(a), "r"(tx) : "memory")
#define MBAR_WAIT(a, par) do {                                                \
    uint32_t _m = (a), _p = (par), _d;                                        \
    asm volatile("{\n\t.reg .pred p;\n\t"                                     \
        "mbarrier.try_wait.parity.acquire.cta.shared::cta.b64 p, [%1], %2;\n\t" \
        "selp.b32 %0, 1, 0, p;\n\t}" : "=r"(_d) : "r"(_m), "r"(_p) : "memory"); \
    if (!_d) {                                                                \
        asm volatile("{\n\t.reg .pred P1;\n\t"                                \
            "WL_%=:\n\t"                                                      \
            "mbarrier.try_wait.parity.acquire.cta.shared::cta.b64 P1, [%0], %1, 0x989680;\n\t" \
            "@P1 bra.uni WD_%=;\n\t"                                          \
            "bra.uni WL_%=;\n\t"                                              \
            "WD_%=:\n\t}" :: "r"(_m), "r"(_p) : "memory");                    \
    }                                                                         \
} while (0)
#define BULK_G2S(dst, src, bytes, mbar) \
    asm volatile("cp.async.bulk.shared::cta.global.mbarrier::complete_tx::bytes " \
                 "[%0], [%1], %2, [%3];" \
                 :: "r"(dst), "l"(src), "r"(bytes), "r"(mbar) : "memory")
#define FENCE_ASYNC() asm volatile("fence.proxy.async.shared::cta;" ::: "memory")

// ---------------------------------------------------------------------------
// Fused QKV projection (tf32 mma). Weight rows stacked [Wv(256); Wq(32); Wk(32)].
// Block: 320 out-rows x 64 n. K=256 in chunks of 64. x transposed in smem.
// ---------------------------------------------------------------------------
#define PQ_SMEM ((64 * 68 + 320 * 68 + 320) * 4)

__global__ __launch_bounds__(256) void proj_qkv_kernel(
    const float* __restrict__ x,
    const float* __restrict__ Wq, const float* __restrict__ bq,
    const float* __restrict__ Wk, const float* __restrict__ bk,
    const float* __restrict__ Wv, const float* __restrict__ bv)
{
    extern __shared__ float smp[];
    float* xT     = smp;                 // [64 n][68]  (p fast)
    float* Ws     = smp + 64 * 68;       // [320 r][68] (p fast)
    float* bias_s = smp + 64 * 68 + 320 * 68;

    const int b   = blockIdx.y;
    const int n0  = blockIdx.x * 64;
    const int tid = threadIdx.x;
    const int w   = tid >> 5;
    const int ln  = tid & 31;
    const int g   = ln >> 2;
    const int t   = ln & 3;
    const int nmt = (w < 4) ? 3 : 2;

    if (tid < 256) bias_s[tid] = bv[tid];
    if (tid < 64)  bias_s[256 + tid] = (tid < 32) ? bq[tid] : bk[tid - 32];

    float4 acc[3][8];
#pragma unroll
    for (int mi = 0; mi < 3; mi++)
#pragma unroll
        for (int ct = 0; ct < 8; ct++) acc[mi][ct] = make_float4(0.f, 0.f, 0.f, 0.f);

    const int xn = tid & 63;
    const int xq0 = tid >> 6;

    for (int p0 = 0; p0 < 256; p0 += 64) {
#pragma unroll
        for (int i = 0; i < 4; i++) {
            const int p = (xq0 + 4 * i) << 2;
            const float* xp = x + (((size_t)((b << 8) + p0 + p)) << 12) + n0 + xn;
            float4 v;
            v.x = xp[0];
            v.y = xp[(size_t)1 << 12];
            v.z = xp[(size_t)2 << 12];
            v.w = xp[(size_t)3 << 12];
            *(float4*)&xT[xn * 68 + p] = v;
        }
#pragma unroll
        for (int it = 0; it < 20; it++) {
            const int idx = tid + (it << 8);
            const int r = idx >> 4, q = idx & 15;
            const float* rp = (r < 256) ? (Wv + r * 256)
                            : (r < 288) ? (Wq + (r - 256) * 256)
                                        : (Wk + (r - 288) * 256);
            *(float4*)&Ws[r * 68 + (q << 2)] = *(const float4*)&rp[p0 + (q << 2)];
        }
        __syncthreads();

#pragma unroll
        for (int kk = 0; kk < 8; kk++) {
            const int k = kk << 3;
            uint32_t bb[8][2], a[3][4];
#pragma unroll
            for (int ct = 0; ct < 8; ct++) {
                const int n = ct * 8 + g;
                bb[ct][0] = __float_as_uint(xT[n * 68 + k + t]);
                bb[ct][1] = __float_as_uint(xT[n * 68 + k + t + 4]);
            }
#pragma unroll
            for (int mi = 0; mi < 3; mi++) {
                if (mi < nmt) {
                    const int rb = (w + 8 * mi) * 16;
                    a[mi][0] = __float_as_uint(Ws[(rb + g) * 68 + k + t]);
                    a[mi][1] = __float_as_uint(Ws[(rb + g + 8) * 68 + k + t]);
                    a[mi][2] = __float_as_uint(Ws[(rb + g) * 68 + k + t + 4]);
                    a[mi][3] = __float_as_uint(Ws[(rb + g + 8) * 68 + k + t + 4]);
                }
            }
#pragma unroll
            for (int mi = 0; mi < 3; mi++)
                if (mi < nmt)
#pragma unroll
                    for (int ct = 0; ct < 8; ct++) mma8(acc[mi][ct], a[mi], bb[ct]);
        }
        __syncthreads();
    }

    auto store1 = [&](int row, int n, float v) {
        v = f2tf(v);
        if (row < 256) {
            g_V[(((size_t)(b * 64 + (n >> 6)) * 256) + row) * 64 +
                ((n & 63) ^ ((row & 7) << 2))] = v;
        } else if (row < 288) {
            g_Qn[(((size_t)b << 12) + n) * 32 + ((row - 256) ^ ((n & 7) << 2))] = v;
        } else {
            g_Km[(((size_t)b << 12) + n) * 32 + ((row - 288) ^ ((n & 7) << 2))] = v;
        }
    };
#pragma unroll
    for (int mi = 0; mi < 3; mi++) {
        if (mi < nmt) {
            const int r0 = (w + 8 * mi) * 16 + g;
            const int r1 = r0 + 8;
            const float b0 = bias_s[r0], b1 = bias_s[r1];
#pragma unroll
            for (int ct = 0; ct < 8; ct++) {
                const int n = n0 + ct * 8 + 2 * t;
                const float4 d = acc[mi][ct];
                store1(r0, n,     d.x + b0);
                store1(r0, n + 1, d.y + b0);
                store1(r1, n,     d.z + b1);
                store1(r1, n + 1, d.w + b1);
            }
        }
    }
}

// ---------------------------------------------------------------------------
// Fused flash attention: per 128-m block, loop 64-n chunks:
//   S = Km·Qn (tf32 mma, Km frags register-resident) -> exp -> P smem tile
//   acc += P·V (tf32 mma, V via bulk-copy pipeline); l accumulated in regs.
// Epilogue: out[b][c][m] = gamma*acc/l[m] + x.
// ---------------------------------------------------------------------------
#define NSTG 2
#define QN_B 8192
#define V_B  65536
#define STG_B (QN_B + V_B)
#define P_OFF 16384
#define STAGE_OFF 49152
#define FU_SMEM (STAGE_OFF + NSTG * STG_B)   // 196608

__global__ __launch_bounds__(256, 1) void attn_fused_kernel(
    const float* __restrict__ xin, const float* __restrict__ gamma,
    float* __restrict__ out)
{
    extern __shared__ float smf[];
    char* sm = (char*)smf;
    __shared__ __align__(8) unsigned long long s_mb[NSTG];
    __shared__ __align__(8) unsigned long long s_mbk;
    __shared__ float s_l[128];

    const int m0 = blockIdx.x * 128;
    const int b  = blockIdx.y;
    const int tid = threadIdx.x;
    const int wid = tid >> 5;
    const int ln  = tid & 31;
    const int g   = ln >> 2;
    const int t   = ln & 3;
    const int mw  = wid & 1;            // PV: 64-m half
    const int cw  = wid >> 1;           // PV: 64-c quarter

    uint32_t mb[NSTG];
#pragma unroll
    for (int s = 0; s < NSTG; s++) mb[s] = smem_u32(&s_mb[s]);
    const uint32_t mbk = smem_u32(&s_mbk);
    const uint32_t smbase = smem_u32(sm);

    const float* Qg = g_Qn + ((size_t)b << 12) * 32;
    const float* Vg = g_V + ((size_t)(b * 64) * C_) * 64;
    const float* Kg = g_Km + (((size_t)b << 12) + m0) * 32;

    if (tid == 0) {
        MBAR_INIT(mbk, 1);
#pragma unroll
        for (int s = 0; s < NSTG; s++) MBAR_INIT(mb[s], 1);
        FENCE_ASYNC();
        MBAR_EXPECT(mbk, 16384);
        BULK_G2S(smbase, Kg, 16384, mbk);
#pragma unroll
        for (int s = 0; s < NSTG; s++) {
            MBAR_EXPECT(mb[s], STG_B);
            BULK_G2S(smbase + STAGE_OFF + s * STG_B,
                     Qg + (size_t)s * 64 * 32, QN_B, mb[s]);
            BULK_G2S(smbase + STAGE_OFF + s * STG_B + QN_B,
                     Vg + (size_t)s * C_ * 64, V_B, mb[s]);
        }
    }
    __syncthreads();
    MBAR_WAIT(mbk, 0);

    // preload Km fragments (S-phase A operand, invariant over chunks)
    const uint32_t* Ku = (const uint32_t*)sm;
    const int rs = wid << 4;            // S-phase m strip [rs, rs+16)
    const uint32_t sx = (uint32_t)(g << 2);
    uint32_t kmf[4][4];
#pragma unroll
    for (int kk = 0; kk < 4; kk++) {
        const int k = kk << 3;
        kmf[kk][0] = Ku[(rs + g) * 32 + ((k + t) ^ sx)];
        kmf[kk][1] = Ku[(rs + g + 8) * 32 + ((k + t) ^ sx)];
        kmf[kk][2] = Ku[(rs + g) * 32 + ((k + t + 4) ^ sx)];
        kmf[kk][3] = Ku[(rs + g + 8) * 32 + ((k + t + 4) ^ sx)];
    }

    float* Pt = (float*)(sm + P_OFF);   // [128 m][64 n'] swizzled
    float4 acc[4][8];
#pragma unroll
    for (int mt = 0; mt < 4; mt++)
#pragma unroll
        for (int ct = 0; ct < 8; ct++) acc[mt][ct] = make_float4(0.f, 0.f, 0.f, 0.f);
    float ls0 = 0.f, ls1 = 0.f;
    int ph[NSTG] = {0, 0};
    const int pr0 = rs + g, pr1 = rs + g + 8;

    for (int ch = 0; ch < 64; ch++) {
        const int st = ch & 1;
        MBAR_WAIT(mb[st], ph[st]);
        ph[st] ^= 1;
        const uint32_t* Qu = (const uint32_t*)(sm + STAGE_OFF + st * STG_B);
        const uint32_t* Vu = (const uint32_t*)(sm + STAGE_OFF + st * STG_B + QN_B);

        // ---- S phase: S[m][n] frags, exp, stash P tile ----
#pragma unroll
        for (int nt = 0; nt < 8; nt++) {
            float4 sa = make_float4(0.f, 0.f, 0.f, 0.f);
            const int nrow = (nt << 3) + g;
#pragma unroll
            for (int kk = 0; kk < 4; kk++) {
                const int k = kk << 3;
                uint32_t bb[2];
                bb[0] = Qu[nrow * 32 + ((k + t) ^ sx)];
                bb[1] = Qu[nrow * 32 + ((k + t + 4) ^ sx)];
                mma8(sa, kmf[kk], bb);
            }
            const float px = f2tf(__expf(sa.x));
            const float py = f2tf(__expf(sa.y));
            const float pz = f2tf(__expf(sa.z));
            const float pw = f2tf(__expf(sa.w));
            ls0 += px + py;
            ls1 += pz + pw;
            const int col = ((nt << 3) + 2 * t) ^ (g << 2);
            *(float2*)&Pt[pr0 * 64 + col] = make_float2(px, py);
            *(float2*)&Pt[pr1 * 64 + col] = make_float2(pz, pw);
        }
        __syncthreads();   // P ready; Qn buffer free

        // ---- PV phase ----
        const uint32_t* Pu = (const uint32_t*)Pt;
#pragma unroll
        for (int kk = 0; kk < 8; kk++) {
            const int k = kk << 3;
            uint32_t a[4][4], bb2[8][2];
#pragma unroll
            for (int mt = 0; mt < 4; mt++) {
                const int rb = mw * 64 + mt * 16;
                a[mt][0] = Pu[(rb + g) * 64 + ((k + t) ^ sx)];
                a[mt][1] = Pu[(rb + g + 8) * 64 + ((k + t) ^ sx)];
                a[mt][2] = Pu[(rb + g) * 64 + ((k + t + 4) ^ sx)];
                a[mt][3] = Pu[(rb + g + 8) * 64 + ((k + t + 4) ^ sx)];
            }
#pragma unroll
            for (int ct = 0; ct < 8; ct++) {
                const int cb = cw * 64 + ct * 8;
                bb2[ct][0] = Vu[(cb + g) * 64 + ((k + t) ^ sx)];
                bb2[ct][1] = Vu[(cb + g) * 64 + ((k + t + 4) ^ sx)];
            }
#pragma unroll
            for (int mt = 0; mt < 4; mt++)
#pragma unroll
                for (int ct = 0; ct < 8; ct++) mma8(acc[mt][ct], a[mt], bb2[ct]);
        }
        __syncthreads();   // V + P buffers free

        if (tid == 0 && ch + NSTG < 64) {
            const int nc = ch + NSTG;
            MBAR_EXPECT(mb[st], STG_B);
            BULK_G2S(smbase + STAGE_OFF + st * STG_B,
                     Qg + (size_t)nc * 64 * 32, QN_B, mb[st]);
            BULK_G2S(smbase + STAGE_OFF + st * STG_B + QN_B,
                     Vg + (size_t)nc * C_ * 64, V_B, mb[st]);
        }
    }

    // ---- l reduction (over t lanes of each quad) ----
    ls0 += __shfl_xor_sync(0xffffffffu, ls0, 1);
    ls0 += __shfl_xor_sync(0xffffffffu, ls0, 2);
    ls1 += __shfl_xor_sync(0xffffffffu, ls1, 1);
    ls1 += __shfl_xor_sync(0xffffffffu, ls1, 2);
    if (t == 0) {
        s_l[pr0] = ls0;
        s_l[pr1] = ls1;
    }
    __syncthreads();

    // ---- epilogue ----
    const float gam = *gamma;
    float il0[4], il1[4];
#pragma unroll
    for (int mt = 0; mt < 4; mt++) {
        const int mm = mw * 64 + mt * 16 + g;
        il0[mt] = 1.0f / s_l[mm];
        il1[mt] = 1.0f / s_l[mm + 8];
    }
#pragma unroll
    for (int mt = 0; mt < 4; mt++) {
        const int m = m0 + mw * 64 + mt * 16 + g;
#pragma unroll
        for (int ct = 0; ct < 8; ct++) {
            const int c = cw * 64 + ct * 8 + 2 * t;
            const float4 d = acc[mt][ct];
            const size_t i00 = (((size_t)(b << 8) + c) << 12) + m;
            const size_t i01 = i00 + N_;
            out[i00]     = gam * d.x * il0[mt] + xin[i00];
            out[i01]     = gam * d.y * il0[mt] + xin[i01];
            out[i00 + 8] = gam * d.z * il1[mt] + xin[i00 + 8];
            out[i01 + 8] = gam * d.w * il1[mt] + xin[i01 + 8];
        }
    }
}

// ---------------------------------------------------------------------------
extern "C" void kernel_launch(void* const* d_in, const int* in_sizes, int n_in,
                              void* d_out, int out_size)
{
    const float* x     = (const float*)d_in[0];
    const float* Wq    = (const float*)d_in[1];
    const float* bq    = (const float*)d_in[2];
    const float* Wk    = (const float*)d_in[3];
    const float* bk    = (const float*)d_in[4];
    const float* Wv    = (const float*)d_in[5];
    const float* bv    = (const float*)d_in[6];
    const float* gamma = (const float*)d_in[7];
    float* out = (float*)d_out;

    static bool attr_set = false;
    if (!attr_set) {
        cudaFuncSetAttribute(proj_qkv_kernel,
            cudaFuncAttributeMaxDynamicSharedMemorySize, PQ_SMEM);
        cudaFuncSetAttribute(attn_fused_kernel,
            cudaFuncAttributeMaxDynamicSharedMemorySize, FU_SMEM);
        attr_set = true;
    }

    proj_qkv_kernel<<<dim3(N_ / 64, B_), 256, PQ_SMEM>>>(
        x, Wq, bq, Wk, bk, Wv, bv);                         // g_Qn, g_Km, g_V
    attn_fused_kernel<<<dim3(N_ / 128, B_), 256, FU_SMEM>>>(x, gamma, out);
}

// round 14
// speedup vs baseline: 1.4385x; 1.4385x over previous
#include <cuda_runtime.h>
#include <cuda_fp16.h>
#include <cstdint>

#define B_   4
#define C_   256
#define N_   4096
#define SOFTMAX_SHIFT 16.0f

// ---------------- device scratch -------------------------------------------
// g_Qn/g_Km: [b][n][j'] j' = j ^ ((n&7)<<2)        (32-float rows, tf32)
// g_Vh: [b][ch64][c][pair'] fp16, rows of 32 half2; pair' = pair ^ ((c&7)<<2)
__device__ float  g_Qn[(size_t)B_ * N_ * 32];
__device__ float  g_Km[(size_t)B_ * N_ * 32];
__device__ __half g_Vh[(size_t)B_ * 64 * C_ * 64];

// ---------------- helpers --------------------------------------------------
__device__ __forceinline__ uint32_t smem_u32(const void* p) {
    uint32_t a;
    asm("{ .reg .u64 t; cvta.to.shared.u64 t, %1; cvt.u32.u64 %0, t; }"
        : "=r"(a) : "l"(p));
    return a;
}
__device__ __forceinline__ float f2tf(float x) {
    uint32_t r;
    asm("cvt.rna.tf32.f32 %0, %1;" : "=r"(r) : "f"(x));
    return __uint_as_float(r);
}
__device__ __forceinline__ void mma8(float4& d, const uint32_t* a, const uint32_t* b) {
    asm("mma.sync.aligned.m16n8k8.row.col.f32.tf32.tf32.f32 "
        "{%0,%1,%2,%3}, {%4,%5,%6,%7}, {%8,%9}, {%0,%1,%2,%3};"
        : "+f"(d.x), "+f"(d.y), "+f"(d.z), "+f"(d.w)
        : "r"(a[0]), "r"(a[1]), "r"(a[2]), "r"(a[3]), "r"(b[0]), "r"(b[1]));
}
__device__ __forceinline__ void mma16h(float4& d, const uint32_t* a, const uint32_t* b) {
    asm("mma.sync.aligned.m16n8k16.row.col.f32.f16.f16.f32 "
        "{%0,%1,%2,%3}, {%4,%5,%6,%7}, {%8,%9}, {%0,%1,%2,%3};"
        : "+f"(d.x), "+f"(d.y), "+f"(d.z), "+f"(d.w)
        : "r"(a[0]), "r"(a[1]), "r"(a[2]), "r"(a[3]), "r"(b[0]), "r"(b[1]));
}
#define MBAR_INIT(a, n) \
    asm volatile("mbarrier.init.shared.b64 [%0], %1;" :: "r"(a), "r"(n) : "memory")
#define MBAR_EXPECT(a, tx) \
    asm volatile("mbarrier.arrive.expect_tx.shared.b64 _, [%0], %1;" \
                 :: "r"(a), "r"(tx) : "memory")
#define MBAR_WAIT(a, par) do {                                                \
    uint32_t _m = (a), _p = (par), _d;                                        \
    asm volatile("{\n\t.reg .pred p;\n\t"                                     \
        "mbarrier.try_wait.parity.acquire.cta.shared::cta.b64 p, [%1], %2;\n\t" \
        "selp.b32 %0, 1, 0, p;\n\t}" : "=r"(_d) : "r"(_m), "r"(_p) : "memory"); \
    if (!_d) {                                                                \
        asm volatile("{\n\t.reg .pred P1;\n\t"                                \
            "WL_%=:\n\t"                                                      \
            "mbarrier.try_wait.parity.acquire.cta.shared::cta.b64 P1, [%0], %1, 0x989680;\n\t" \
            "@P1 bra.uni WD_%=;\n\t"                                          \
            "bra.uni WL_%=;\n\t"                                              \
            "WD_%=:\n\t}" :: "r"(_m), "r"(_p) : "memory");                    \
    }                                                                         \
} while (0)
#define BULK_G2S(dst, src, bytes, mbar) \
    asm volatile("cp.async.bulk.shared::cta.global.mbarrier::complete_tx::bytes " \
                 "[%0], [%1], %2, [%3];" \
                 :: "r"(dst), "l"(src), "r"(bytes), "r"(mbar) : "memory")
#define FENCE_ASYNC() asm volatile("fence.proxy.async.shared::cta;" ::: "memory")

// ---------------------------------------------------------------------------
// Fused QKV projection (tf32 mma). Weight rows stacked [Wv(256); Wq(32); Wk(32)].
// V written as fp16 (pair-swizzled); Q/K written tf32-rounded fp32.
// ---------------------------------------------------------------------------
#define PQ_SMEM ((64 * 68 + 320 * 68 + 320) * 4)

__global__ __launch_bounds__(256) void proj_qkv_kernel(
    const float* __restrict__ x,
    const float* __restrict__ Wq, const float* __restrict__ bq,
    const float* __restrict__ Wk, const float* __restrict__ bk,
    const float* __restrict__ Wv, const float* __restrict__ bv)
{
    extern __shared__ float smp[];
    float* xT     = smp;                 // [64 n][68]  (p fast)
    float* Ws     = smp + 64 * 68;       // [320 r][68] (p fast)
    float* bias_s = smp + 64 * 68 + 320 * 68;

    const int b   = blockIdx.y;
    const int n0  = blockIdx.x * 64;
    const int tid = threadIdx.x;
    const int w   = tid >> 5;
    const int ln  = tid & 31;
    const int g   = ln >> 2;
    const int t   = ln & 3;
    const int nmt = (w < 4) ? 3 : 2;

    if (tid < 256) bias_s[tid] = bv[tid];
    if (tid < 64)  bias_s[256 + tid] = (tid < 32) ? bq[tid] : bk[tid - 32];

    float4 acc[3][8];
#pragma unroll
    for (int mi = 0; mi < 3; mi++)
#pragma unroll
        for (int ct = 0; ct < 8; ct++) acc[mi][ct] = make_float4(0.f, 0.f, 0.f, 0.f);

    const int xn = tid & 63;
    const int xq0 = tid >> 6;

    for (int p0 = 0; p0 < 256; p0 += 64) {
#pragma unroll
        for (int i = 0; i < 4; i++) {
            const int p = (xq0 + 4 * i) << 2;
            const float* xp = x + (((size_t)((b << 8) + p0 + p)) << 12) + n0 + xn;
            float4 v;
            v.x = xp[0];
            v.y = xp[(size_t)1 << 12];
            v.z = xp[(size_t)2 << 12];
            v.w = xp[(size_t)3 << 12];
            *(float4*)&xT[xn * 68 + p] = v;
        }
#pragma unroll
        for (int it = 0; it < 20; it++) {
            const int idx = tid + (it << 8);
            const int r = idx >> 4, q = idx & 15;
            const float* rp = (r < 256) ? (Wv + r * 256)
                            : (r < 288) ? (Wq + (r - 256) * 256)
                                        : (Wk + (r - 288) * 256);
            *(float4*)&Ws[r * 68 + (q << 2)] = *(const float4*)&rp[p0 + (q << 2)];
        }
        __syncthreads();

#pragma unroll
        for (int kk = 0; kk < 8; kk++) {
            const int k = kk << 3;
            uint32_t bb[8][2], a[3][4];
#pragma unroll
            for (int ct = 0; ct < 8; ct++) {
                const int n = ct * 8 + g;
                bb[ct][0] = __float_as_uint(xT[n * 68 + k + t]);
                bb[ct][1] = __float_as_uint(xT[n * 68 + k + t + 4]);
            }
#pragma unroll
            for (int mi = 0; mi < 3; mi++) {
                if (mi < nmt) {
                    const int rb = (w + 8 * mi) * 16;
                    a[mi][0] = __float_as_uint(Ws[(rb + g) * 68 + k + t]);
                    a[mi][1] = __float_as_uint(Ws[(rb + g + 8) * 68 + k + t]);
                    a[mi][2] = __float_as_uint(Ws[(rb + g) * 68 + k + t + 4]);
                    a[mi][3] = __float_as_uint(Ws[(rb + g + 8) * 68 + k + t + 4]);
                }
            }
#pragma unroll
            for (int mi = 0; mi < 3; mi++)
                if (mi < nmt)
#pragma unroll
                    for (int ct = 0; ct < 8; ct++) mma8(acc[mi][ct], a[mi], bb[ct]);
        }
        __syncthreads();
    }

    // V rows: half2 pair-swizzled store. Q/K rows: tf32-rounded fp32 store.
    auto storeQK = [&](int row, int n, float v) {
        v = f2tf(v);
        if (row < 288)
            g_Qn[(((size_t)b << 12) + n) * 32 + ((row - 256) ^ ((n & 7) << 2))] = v;
        else
            g_Km[(((size_t)b << 12) + n) * 32 + ((row - 288) ^ ((n & 7) << 2))] = v;
    };
#pragma unroll
    for (int mi = 0; mi < 3; mi++) {
        if (mi < nmt) {
            const int r0 = (w + 8 * mi) * 16 + g;
            const int r1 = r0 + 8;
            const float b0 = bias_s[r0], b1 = bias_s[r1];
#pragma unroll
            for (int ct = 0; ct < 8; ct++) {
                const int n = n0 + ct * 8 + 2 * t;      // even
                const float4 d = acc[mi][ct];
                if (r0 < 256) {
                    const int ch = n >> 6;
                    const int pr0 = ((n & 63) >> 1) ^ ((r0 & 7) << 2);
                    const int pr1 = ((n & 63) >> 1) ^ ((r1 & 7) << 2);
                    __half2* vb = (__half2*)g_Vh +
                        ((size_t)(b * 64 + ch) * 256) * 32;
                    vb[(size_t)r0 * 32 + pr0] = __floats2half2_rn(d.x + b0, d.y + b0);
                    vb[(size_t)r1 * 32 + pr1] = __floats2half2_rn(d.z + b1, d.w + b1);
                } else {
                    storeQK(r0, n,     d.x + b0);
                    storeQK(r0, n + 1, d.y + b0);
                    storeQK(r1, n,     d.z + b1);
                    storeQK(r1, n + 1, d.w + b1);
                }
            }
        }
    }
}

// ---------------------------------------------------------------------------
// Fused flash attention. Per 128-m block, 64-n chunks:
//   S = Km·Qn (tf32 mma, Km frags in regs) -> exp(s - SHIFT) -> fp16 P tile
//   acc += P·V (fp16 m16n8k16 mma, V via 3-stage bulk pipeline)
// Shift cancels in out = gamma * (P·V)/l + x  since l sums the same shifted p.
// ---------------------------------------------------------------------------
#define NSTG 3
#define QN_B 8192
#define V_B  32768
#define STG_B (QN_B + V_B)
#define P_OFF 16384
#define STAGE_OFF 32768
#define FU_SMEM (STAGE_OFF + NSTG * STG_B)   // 155648

__global__ __launch_bounds__(256, 1) void attn_fused_kernel(
    const float* __restrict__ xin, const float* __restrict__ gamma,
    float* __restrict__ out)
{
    extern __shared__ float smf[];
    char* sm = (char*)smf;
    __shared__ __align__(8) unsigned long long s_mb[NSTG];
    __shared__ __align__(8) unsigned long long s_mbk;
    __shared__ float s_l[128];

    const int m0 = blockIdx.x * 128;
    const int b  = blockIdx.y;
    const int tid = threadIdx.x;
    const int wid = tid >> 5;
    const int ln  = tid & 31;
    const int g   = ln >> 2;
    const int t   = ln & 3;
    const int mw  = wid & 1;            // PV: 64-m half
    const int cw  = wid >> 1;           // PV: 64-c quarter

    uint32_t mb[NSTG];
#pragma unroll
    for (int s = 0; s < NSTG; s++) mb[s] = smem_u32(&s_mb[s]);
    const uint32_t mbk = smem_u32(&s_mbk);
    const uint32_t smbase = smem_u32(sm);

    const float*  Qg = g_Qn + ((size_t)b << 12) * 32;
    const __half* Vg = g_Vh + ((size_t)(b * 64) * C_) * 64;
    const float*  Kg = g_Km + (((size_t)b << 12) + m0) * 32;

    if (tid == 0) {
        MBAR_INIT(mbk, 1);
#pragma unroll
        for (int s = 0; s < NSTG; s++) MBAR_INIT(mb[s], 1);
        FENCE_ASYNC();
        MBAR_EXPECT(mbk, 16384);
        BULK_G2S(smbase, Kg, 16384, mbk);
#pragma unroll
        for (int s = 0; s < NSTG; s++) {
            MBAR_EXPECT(mb[s], STG_B);
            BULK_G2S(smbase + STAGE_OFF + s * STG_B,
                     Qg + (size_t)s * 64 * 32, QN_B, mb[s]);
            BULK_G2S(smbase + STAGE_OFF + s * STG_B + QN_B,
                     Vg + (size_t)s * C_ * 64, V_B, mb[s]);
        }
    }
    __syncthreads();
    MBAR_WAIT(mbk, 0);

    // preload Km fragments (S-phase A operand, invariant over chunks)
    const uint32_t* Ku = (const uint32_t*)sm;
    const int rs = wid << 4;            // S-phase m strip [rs, rs+16)
    const uint32_t sx = (uint32_t)(g << 2);
    uint32_t kmf[4][4];
#pragma unroll
    for (int kk = 0; kk < 4; kk++) {
        const int k = kk << 3;
        kmf[kk][0] = Ku[(rs + g) * 32 + ((k + t) ^ sx)];
        kmf[kk][1] = Ku[(rs + g + 8) * 32 + ((k + t) ^ sx)];
        kmf[kk][2] = Ku[(rs + g) * 32 + ((k + t + 4) ^ sx)];
        kmf[kk][3] = Ku[(rs + g + 8) * 32 + ((k + t + 4) ^ sx)];
    }

    __half2*  Pth = (__half2*)(sm + P_OFF);       // [128 m][32 pairs] swizzled
    uint32_t* Ptu = (uint32_t*)(sm + P_OFF);
    float4 acc[4][8];
#pragma unroll
    for (int mt = 0; mt < 4; mt++)
#pragma unroll
        for (int ct = 0; ct < 8; ct++) acc[mt][ct] = make_float4(0.f, 0.f, 0.f, 0.f);
    float ls0 = 0.f, ls1 = 0.f;
    int ph[NSTG] = {0, 0, 0};
    const int pr0 = rs + g, pr1 = rs + g + 8;     // pr0&7 == pr1&7 == g

    for (int ch = 0; ch < 64; ch++) {
        const int st = ch % NSTG;
        MBAR_WAIT(mb[st], ph[st]);
        ph[st] ^= 1;
        const uint32_t* Qu  = (const uint32_t*)(sm + STAGE_OFF + st * STG_B);
        const uint32_t* Vuh = (const uint32_t*)(sm + STAGE_OFF + st * STG_B + QN_B);

        // ---- S phase: tf32 mma, shifted exp, stash fp16 P tile ----
#pragma unroll
        for (int nt = 0; nt < 8; nt++) {
            float4 sa = make_float4(0.f, 0.f, 0.f, 0.f);
            const int nrow = (nt << 3) + g;
#pragma unroll
            for (int kk = 0; kk < 4; kk++) {
                const int k = kk << 3;
                uint32_t bb[2];
                bb[0] = Qu[nrow * 32 + ((k + t) ^ sx)];
                bb[1] = Qu[nrow * 32 + ((k + t + 4) ^ sx)];
                mma8(sa, kmf[kk], bb);
            }
            const __half2 h0 = __floats2half2_rn(__expf(sa.x - SOFTMAX_SHIFT),
                                                 __expf(sa.y - SOFTMAX_SHIFT));
            const __half2 h1 = __floats2half2_rn(__expf(sa.z - SOFTMAX_SHIFT),
                                                 __expf(sa.w - SOFTMAX_SHIFT));
            const float2 f0 = __half22float2(h0);
            const float2 f1 = __half22float2(h1);
            ls0 += f0.x + f0.y;
            ls1 += f1.x + f1.y;
            const int pair = ((nt << 2) + t) ^ sx;   // (nt*8+2t)/2 ^ (g<<2)
            Pth[pr0 * 32 + pair] = h0;
            Pth[pr1 * 32 + pair] = h1;
        }
        __syncthreads();   // P ready

        // ---- PV phase: fp16 m16n8k16 ----
#pragma unroll
        for (int kk = 0; kk < 4; kk++) {
            const int kb = kk << 3;                  // pair base (16 k = 8 pairs)
            uint32_t a[4][4], bb2[8][2];
#pragma unroll
            for (int mt = 0; mt < 4; mt++) {
                const int rb = mw * 64 + mt * 16;
                a[mt][0] = Ptu[(rb + g) * 32 + ((kb + t) ^ sx)];
                a[mt][1] = Ptu[(rb + g + 8) * 32 + ((kb + t) ^ sx)];
                a[mt][2] = Ptu[(rb + g) * 32 + ((kb + 4 + t) ^ sx)];
                a[mt][3] = Ptu[(rb + g + 8) * 32 + ((kb + 4 + t) ^ sx)];
            }
#pragma unroll
            for (int ct = 0; ct < 8; ct++) {
                const int cb = cw * 64 + ct * 8;
                bb2[ct][0] = Vuh[(cb + g) * 32 + ((kb + t) ^ sx)];
                bb2[ct][1] = Vuh[(cb + g) * 32 + ((kb + 4 + t) ^ sx)];
            }
#pragma unroll
            for (int mt = 0; mt < 4; mt++)
#pragma unroll
                for (int ct = 0; ct < 8; ct++) mma16h(acc[mt][ct], a[mt], bb2[ct]);
        }
        __syncthreads();   // V + P buffers free

        if (tid == 0 && ch + NSTG < 64) {
            const int nc = ch + NSTG;
            MBAR_EXPECT(mb[st], STG_B);
            BULK_G2S(smbase + STAGE_OFF + st * STG_B,
                     Qg + (size_t)nc * 64 * 32, QN_B, mb[st]);
            BULK_G2S(smbase + STAGE_OFF + st * STG_B + QN_B,
                     Vg + (size_t)nc * C_ * 64, V_B, mb[st]);
        }
    }

    // ---- l reduction (t lanes of each quad hold disjoint n slices) ----
    ls0 += __shfl_xor_sync(0xffffffffu, ls0, 1);
    ls0 += __shfl_xor_sync(0xffffffffu, ls0, 2);
    ls1 += __shfl_xor_sync(0xffffffffu, ls1, 1);
    ls1 += __shfl_xor_sync(0xffffffffu, ls1, 2);
    if (t == 0) {
        s_l[pr0] = ls0;
        s_l[pr1] = ls1;
    }
    __syncthreads();

    // ---- epilogue ----
    const float gam = *gamma;
    float il0[4], il1[4];
#pragma unroll
    for (int mt = 0; mt < 4; mt++) {
        const int mm = mw * 64 + mt * 16 + g;
        il0[mt] = 1.0f / s_l[mm];
        il1[mt] = 1.0f / s_l[mm + 8];
    }
#pragma unroll
    for (int mt = 0; mt < 4; mt++) {
        const int m = m0 + mw * 64 + mt * 16 + g;
#pragma unroll
        for (int ct = 0; ct < 8; ct++) {
            const int c = cw * 64 + ct * 8 + 2 * t;
            const float4 d = acc[mt][ct];
            const size_t i00 = (((size_t)(b << 8) + c) << 12) + m;
            const size_t i01 = i00 + N_;
            out[i00]     = gam * d.x * il0[mt] + xin[i00];
            out[i01]     = gam * d.y * il0[mt] + xin[i01];
            out[i00 + 8] = gam * d.z * il1[mt] + xin[i00 + 8];
            out[i01 + 8] = gam * d.w * il1[mt] + xin[i01 + 8];
        }
    }
}

// ---------------------------------------------------------------------------
extern "C" void kernel_launch(void* const* d_in, const int* in_sizes, int n_in,
                              void* d_out, int out_size)
{
    const float* x     = (const float*)d_in[0];
    const float* Wq    = (const float*)d_in[1];
    const float* bq    = (const float*)d_in[2];
    const float* Wk    = (const float*)d_in[3];
    const float* bk    = (const float*)d_in[4];
    const float* Wv    = (const float*)d_in[5];
    const float* bv    = (const float*)d_in[6];
    const float* gamma = (const float*)d_in[7];
    float* out = (float*)d_out;

    static bool attr_set = false;
    if (!attr_set) {
        cudaFuncSetAttribute(proj_qkv_kernel,
            cudaFuncAttributeMaxDynamicSharedMemorySize, PQ_SMEM);
        cudaFuncSetAttribute(attn_fused_kernel,
            cudaFuncAttributeMaxDynamicSharedMemorySize, FU_SMEM);
        attr_set = true;
    }

    proj_qkv_kernel<<<dim3(N_ / 64, B_), 256, PQ_SMEM>>>(
        x, Wq, bq, Wk, bk, Wv, bv);                         // g_Qn, g_Km, g_Vh
    attn_fused_kernel<<<dim3(N_ / 128, B_), 256, FU_SMEM>>>(x, gamma, out);
}

// round 15
// speedup vs baseline: 1.5190x; 1.0560x over previous
#include <cuda_runtime.h>
#include <cuda_fp16.h>
#include <cstdint>

#define B_   4
#define C_   256
#define N_   4096
#define SOFTMAX_SHIFT 16.0f

// ---------------- device scratch -------------------------------------------
// g_Qn/g_Km: [b][n][j'] j' = j ^ ((n&7)<<2)        (32-float rows, tf32)
// g_Vh: [b][ch64][c][pair'] fp16, rows of 32 half2; pair' = pair ^ ((c&7)<<2)
__device__ float  g_Qn[(size_t)B_ * N_ * 32];
__device__ float  g_Km[(size_t)B_ * N_ * 32];
__device__ __half g_Vh[(size_t)B_ * 64 * C_ * 64];

// ---------------- helpers --------------------------------------------------
__device__ __forceinline__ uint32_t smem_u32(const void* p) {
    uint32_t a;
    asm("{ .reg .u64 t; cvta.to.shared.u64 t, %1; cvt.u32.u64 %0, t; }"
        : "=r"(a) : "l"(p));
    return a;
}
__device__ __forceinline__ float f2tf(float x) {
    uint32_t r;
    asm("cvt.rna.tf32.f32 %0, %1;" : "=r"(r) : "f"(x));
    return __uint_as_float(r);
}
__device__ __forceinline__ void mma8(float4& d, const uint32_t* a, const uint32_t* b) {
    asm("mma.sync.aligned.m16n8k8.row.col.f32.tf32.tf32.f32 "
        "{%0,%1,%2,%3}, {%4,%5,%6,%7}, {%8,%9}, {%0,%1,%2,%3};"
        : "+f"(d.x), "+f"(d.y), "+f"(d.z), "+f"(d.w)
        : "r"(a[0]), "r"(a[1]), "r"(a[2]), "r"(a[3]), "r"(b[0]), "r"(b[1]));
}
__device__ __forceinline__ void mma16h(float4& d, const uint32_t* a, const uint32_t* b) {
    asm("mma.sync.aligned.m16n8k16.row.col.f32.f16.f16.f32 "
        "{%0,%1,%2,%3}, {%4,%5,%6,%7}, {%8,%9}, {%0,%1,%2,%3};"
        : "+f"(d.x), "+f"(d.y), "+f"(d.z), "+f"(d.w)
        : "r"(a[0]), "r"(a[1]), "r"(a[2]), "r"(a[3]), "r"(b[0]), "r"(b[1]));
}
#define MBAR_INIT(a, n) \
    asm volatile("mbarrier.init.shared.b64 [%0], %1;" :: "r"(a), "r"(n) : "memory")
#define MBAR_EXPECT(a, tx) \
    asm volatile("mbarrier.arrive.expect_tx.shared.b64 _, [%0], %1;" \
                 :: "r"(a), "r"(tx) : "memory")
#define MBAR_WAIT(a, par) do {                                                \
    uint32_t _m = (a), _p = (par), _d;                                        \
    asm volatile("{\n\t.reg .pred p;\n\t"                                     \
        "mbarrier.try_wait.parity.acquire.cta.shared::cta.b64 p, [%1], %2;\n\t" \
        "selp.b32 %0, 1, 0, p;\n\t}" : "=r"(_d) : "r"(_m), "r"(_p) : "memory"); \
    if (!_d) {                                                                \
        asm volatile("{\n\t.reg .pred P1;\n\t"                                \
            "WL_%=:\n\t"                                                      \
            "mbarrier.try_wait.parity.acquire.cta.shared::cta.b64 P1, [%0], %1, 0x989680;\n\t" \
            "@P1 bra.uni WD_%=;\n\t"                                          \
            "bra.uni WL_%=;\n\t"                                              \
            "WD_%=:\n\t}" :: "r"(_m), "r"(_p) : "memory");                    \
    }                                                                         \
} while (0)
#define BULK_G2S(dst, src, bytes, mbar) \
    asm volatile("cp.async.bulk.shared::cta.global.mbarrier::complete_tx::bytes " \
                 "[%0], [%1], %2, [%3];" \
                 :: "r"(dst), "l"(src), "r"(bytes), "r"(mbar) : "memory")
#define FENCE_ASYNC() asm volatile("fence.proxy.async.shared::cta;" ::: "memory")

// ---------------------------------------------------------------------------
// Fused QKV projection (tf32 mma). Weight rows stacked [Wv(256); Wq(32); Wk(32)].
// V written as fp16 (pair-swizzled); Q/K written tf32-rounded fp32.
// ---------------------------------------------------------------------------
#define PQ_SMEM ((64 * 68 + 320 * 68 + 320) * 4)

__global__ __launch_bounds__(256) void proj_qkv_kernel(
    const float* __restrict__ x,
    const float* __restrict__ Wq, const float* __restrict__ bq,
    const float* __restrict__ Wk, const float* __restrict__ bk,
    const float* __restrict__ Wv, const float* __restrict__ bv)
{
    extern __shared__ float smp[];
    float* xT     = smp;                 // [64 n][68]  (p fast)
    float* Ws     = smp + 64 * 68;       // [320 r][68] (p fast)
    float* bias_s = smp + 64 * 68 + 320 * 68;

    const int b   = blockIdx.y;
    const int n0  = blockIdx.x * 64;
    const int tid = threadIdx.x;
    const int w   = tid >> 5;
    const int ln  = tid & 31;
    const int g   = ln >> 2;
    const int t   = ln & 3;
    const int nmt = (w < 4) ? 3 : 2;

    if (tid < 256) bias_s[tid] = bv[tid];
    if (tid < 64)  bias_s[256 + tid] = (tid < 32) ? bq[tid] : bk[tid - 32];

    float4 acc[3][8];
#pragma unroll
    for (int mi = 0; mi < 3; mi++)
#pragma unroll
        for (int ct = 0; ct < 8; ct++) acc[mi][ct] = make_float4(0.f, 0.f, 0.f, 0.f);

    const int xn = tid & 63;
    const int xq0 = tid >> 6;

    for (int p0 = 0; p0 < 256; p0 += 64) {
#pragma unroll
        for (int i = 0; i < 4; i++) {
            const int p = (xq0 + 4 * i) << 2;
            const float* xp = x + (((size_t)((b << 8) + p0 + p)) << 12) + n0 + xn;
            float4 v;
            v.x = xp[0];
            v.y = xp[(size_t)1 << 12];
            v.z = xp[(size_t)2 << 12];
            v.w = xp[(size_t)3 << 12];
            *(float4*)&xT[xn * 68 + p] = v;
        }
#pragma unroll
        for (int it = 0; it < 20; it++) {
            const int idx = tid + (it << 8);
            const int r = idx >> 4, q = idx & 15;
            const float* rp = (r < 256) ? (Wv + r * 256)
                            : (r < 288) ? (Wq + (r - 256) * 256)
                                        : (Wk + (r - 288) * 256);
            *(float4*)&Ws[r * 68 + (q << 2)] = *(const float4*)&rp[p0 + (q << 2)];
        }
        __syncthreads();

#pragma unroll
        for (int kk = 0; kk < 8; kk++) {
            const int k = kk << 3;
            uint32_t bb[8][2], a[3][4];
#pragma unroll
            for (int ct = 0; ct < 8; ct++) {
                const int n = ct * 8 + g;
                bb[ct][0] = __float_as_uint(xT[n * 68 + k + t]);
                bb[ct][1] = __float_as_uint(xT[n * 68 + k + t + 4]);
            }
#pragma unroll
            for (int mi = 0; mi < 3; mi++) {
                if (mi < nmt) {
                    const int rb = (w + 8 * mi) * 16;
                    a[mi][0] = __float_as_uint(Ws[(rb + g) * 68 + k + t]);
                    a[mi][1] = __float_as_uint(Ws[(rb + g + 8) * 68 + k + t]);
                    a[mi][2] = __float_as_uint(Ws[(rb + g) * 68 + k + t + 4]);
                    a[mi][3] = __float_as_uint(Ws[(rb + g + 8) * 68 + k + t + 4]);
                }
            }
#pragma unroll
            for (int mi = 0; mi < 3; mi++)
                if (mi < nmt)
#pragma unroll
                    for (int ct = 0; ct < 8; ct++) mma8(acc[mi][ct], a[mi], bb[ct]);
        }
        __syncthreads();
    }

    auto storeQK = [&](int row, int n, float v) {
        v = f2tf(v);
        if (row < 288)
            g_Qn[(((size_t)b << 12) + n) * 32 + ((row - 256) ^ ((n & 7) << 2))] = v;
        else
            g_Km[(((size_t)b << 12) + n) * 32 + ((row - 288) ^ ((n & 7) << 2))] = v;
    };
#pragma unroll
    for (int mi = 0; mi < 3; mi++) {
        if (mi < nmt) {
            const int r0 = (w + 8 * mi) * 16 + g;
            const int r1 = r0 + 8;
            const float b0 = bias_s[r0], b1 = bias_s[r1];
#pragma unroll
            for (int ct = 0; ct < 8; ct++) {
                const int n = n0 + ct * 8 + 2 * t;      // even
                const float4 d = acc[mi][ct];
                if (r0 < 256) {
                    const int ch = n >> 6;
                    const int pr0 = ((n & 63) >> 1) ^ ((r0 & 7) << 2);
                    const int pr1 = ((n & 63) >> 1) ^ ((r1 & 7) << 2);
                    __half2* vb = (__half2*)g_Vh +
                        ((size_t)(b * 64 + ch) * 256) * 32;
                    vb[(size_t)r0 * 32 + pr0] = __floats2half2_rn(d.x + b0, d.y + b0);
                    vb[(size_t)r1 * 32 + pr1] = __floats2half2_rn(d.z + b1, d.w + b1);
                } else {
                    storeQK(r0, n,     d.x + b0);
                    storeQK(r0, n + 1, d.y + b0);
                    storeQK(r1, n,     d.z + b1);
                    storeQK(r1, n + 1, d.w + b1);
                }
            }
        }
    }
}

// ---------------------------------------------------------------------------
// Fused flash attention, BM=64 / 2 CTAs per SM. Per 64-m block, 64-n chunks:
//   S[64m][64n] = Km·Qn (tf32; warp w -> m-tile (w&3), n-half (w>>2))
//   exp(s-SHIFT) -> fp16 P tile; acc += P·V (fp16; warp w -> m-half (w&1),
//   c-quarter (w>>1)); l via 2-part smem reduction.
// ---------------------------------------------------------------------------
#define NSTG 2
#define QN_B 8192
#define V_B  32768
#define STG_B (QN_B + V_B)
#define P_OFF 8192
#define STAGE_OFF 16384
#define FU_SMEM (STAGE_OFF + NSTG * STG_B)   // 98304

__global__ __launch_bounds__(256, 2) void attn_fused_kernel(
    const float* __restrict__ xin, const float* __restrict__ gamma,
    float* __restrict__ out)
{
    extern __shared__ float smf[];
    char* sm = (char*)smf;
    __shared__ __align__(8) unsigned long long s_mb[NSTG];
    __shared__ __align__(8) unsigned long long s_mbk;
    __shared__ float s_lp[2][64];

    const int m0 = blockIdx.x * 64;
    const int b  = blockIdx.y;
    const int tid = threadIdx.x;
    const int wid = tid >> 5;
    const int ln  = tid & 31;
    const int g   = ln >> 2;
    const int t   = ln & 3;
    // S roles
    const int rs     = (wid & 3) << 4;   // m-tile base
    const int n_base = (wid >> 2) << 5;  // n-half base
    // PV roles
    const int pm = (wid & 1) << 5;       // m-half
    const int pc = (wid >> 1) << 6;      // c-quarter

    uint32_t mb[NSTG];
#pragma unroll
    for (int s = 0; s < NSTG; s++) mb[s] = smem_u32(&s_mb[s]);
    const uint32_t mbk = smem_u32(&s_mbk);
    const uint32_t smbase = smem_u32(sm);

    const float*  Qg = g_Qn + ((size_t)b << 12) * 32;
    const __half* Vg = g_Vh + ((size_t)(b * 64) * C_) * 64;
    const float*  Kg = g_Km + (((size_t)b << 12) + m0) * 32;

    if (tid == 0) {
        MBAR_INIT(mbk, 1);
#pragma unroll
        for (int s = 0; s < NSTG; s++) MBAR_INIT(mb[s], 1);
        FENCE_ASYNC();
        MBAR_EXPECT(mbk, 8192);
        BULK_G2S(smbase, Kg, 8192, mbk);
#pragma unroll
        for (int s = 0; s < NSTG; s++) {
            MBAR_EXPECT(mb[s], STG_B);
            BULK_G2S(smbase + STAGE_OFF + s * STG_B,
                     Qg + (size_t)s * 64 * 32, QN_B, mb[s]);
            BULK_G2S(smbase + STAGE_OFF + s * STG_B + QN_B,
                     Vg + (size_t)s * C_ * 64, V_B, mb[s]);
        }
    }
    __syncthreads();
    MBAR_WAIT(mbk, 0);

    // preload Km fragments (S-phase A operand, invariant over chunks)
    const uint32_t* Ku = (const uint32_t*)sm;
    const uint32_t sx = (uint32_t)(g << 2);
    uint32_t kmf[4][4];
#pragma unroll
    for (int kk = 0; kk < 4; kk++) {
        const int k = kk << 3;
        kmf[kk][0] = Ku[(rs + g) * 32 + ((k + t) ^ sx)];
        kmf[kk][1] = Ku[(rs + g + 8) * 32 + ((k + t) ^ sx)];
        kmf[kk][2] = Ku[(rs + g) * 32 + ((k + t + 4) ^ sx)];
        kmf[kk][3] = Ku[(rs + g + 8) * 32 + ((k + t + 4) ^ sx)];
    }

    __half2*  Pth = (__half2*)(sm + P_OFF);       // [64 m][32 pairs] swizzled
    uint32_t* Ptu = (uint32_t*)(sm + P_OFF);
    float4 acc[2][8];
#pragma unroll
    for (int mt = 0; mt < 2; mt++)
#pragma unroll
        for (int ct = 0; ct < 8; ct++) acc[mt][ct] = make_float4(0.f, 0.f, 0.f, 0.f);
    float ls0 = 0.f, ls1 = 0.f;
    int ph[NSTG] = {0, 0};
    const int pr0 = rs + g, pr1 = rs + g + 8;     // pr0&7 == pr1&7 == g

    for (int ch = 0; ch < 64; ch++) {
        const int st = ch & 1;
        MBAR_WAIT(mb[st], ph[st]);
        ph[st] ^= 1;
        const uint32_t* Qu  = (const uint32_t*)(sm + STAGE_OFF + st * STG_B);
        const uint32_t* Vuh = (const uint32_t*)(sm + STAGE_OFF + st * STG_B + QN_B);

        // ---- S phase: tf32 mma on [16 m][32 n] slice, shifted exp ----
#pragma unroll
        for (int nt = 0; nt < 4; nt++) {
            float4 sa = make_float4(0.f, 0.f, 0.f, 0.f);
            const int nrow = n_base + (nt << 3) + g;
#pragma unroll
            for (int kk = 0; kk < 4; kk++) {
                const int k = kk << 3;
                uint32_t bb[2];
                bb[0] = Qu[nrow * 32 + ((k + t) ^ sx)];
                bb[1] = Qu[nrow * 32 + ((k + t + 4) ^ sx)];
                mma8(sa, kmf[kk], bb);
            }
            const __half2 h0 = __floats2half2_rn(__expf(sa.x - SOFTMAX_SHIFT),
                                                 __expf(sa.y - SOFTMAX_SHIFT));
            const __half2 h1 = __floats2half2_rn(__expf(sa.z - SOFTMAX_SHIFT),
                                                 __expf(sa.w - SOFTMAX_SHIFT));
            const float2 f0 = __half22float2(h0);
            const float2 f1 = __half22float2(h1);
            ls0 += f0.x + f0.y;
            ls1 += f1.x + f1.y;
            const int pair = ((n_base >> 1) + (nt << 2) + t) ^ sx;
            Pth[pr0 * 32 + pair] = h0;
            Pth[pr1 * 32 + pair] = h1;
        }
        __syncthreads();   // P ready

        // ---- PV phase: fp16 m16n8k16 on [32 m][64 c] slice ----
#pragma unroll
        for (int kk = 0; kk < 4; kk++) {
            const int kb = kk << 3;                  // pair base (16 k = 8 pairs)
            uint32_t a[2][4], bb2[8][2];
#pragma unroll
            for (int mt = 0; mt < 2; mt++) {
                const int rb = pm + (mt << 4);
                a[mt][0] = Ptu[(rb + g) * 32 + ((kb + t) ^ sx)];
                a[mt][1] = Ptu[(rb + g + 8) * 32 + ((kb + t) ^ sx)];
                a[mt][2] = Ptu[(rb + g) * 32 + ((kb + 4 + t) ^ sx)];
                a[mt][3] = Ptu[(rb + g + 8) * 32 + ((kb + 4 + t) ^ sx)];
            }
#pragma unroll
            for (int ct = 0; ct < 8; ct++) {
                const int cb = pc + (ct << 3);
                bb2[ct][0] = Vuh[(cb + g) * 32 + ((kb + t) ^ sx)];
                bb2[ct][1] = Vuh[(cb + g) * 32 + ((kb + 4 + t) ^ sx)];
            }
#pragma unroll
            for (int mt = 0; mt < 2; mt++)
#pragma unroll
                for (int ct = 0; ct < 8; ct++) mma16h(acc[mt][ct], a[mt], bb2[ct]);
        }
        __syncthreads();   // V + P buffers free

        if (tid == 0 && ch + NSTG < 64) {
            const int nc = ch + NSTG;
            MBAR_EXPECT(mb[st], STG_B);
            BULK_G2S(smbase + STAGE_OFF + st * STG_B,
                     Qg + (size_t)nc * 64 * 32, QN_B, mb[st]);
            BULK_G2S(smbase + STAGE_OFF + st * STG_B + QN_B,
                     Vg + (size_t)nc * C_ * 64, V_B, mb[st]);
        }
    }

    // ---- l reduction: quad-lane sum, then combine the two n-halves ----
    ls0 += __shfl_xor_sync(0xffffffffu, ls0, 1);
    ls0 += __shfl_xor_sync(0xffffffffu, ls0, 2);
    ls1 += __shfl_xor_sync(0xffffffffu, ls1, 1);
    ls1 += __shfl_xor_sync(0xffffffffu, ls1, 2);
    if (t == 0) {
        s_lp[wid >> 2][pr0] = ls0;
        s_lp[wid >> 2][pr1] = ls1;
    }
    __syncthreads();

    // ---- epilogue ----
    const float gam = *gamma;
    float il0[2], il1[2];
#pragma unroll
    for (int mt = 0; mt < 2; mt++) {
        const int mm = pm + (mt << 4) + g;
        il0[mt] = 1.0f / (s_lp[0][mm] + s_lp[1][mm]);
        il1[mt] = 1.0f / (s_lp[0][mm + 8] + s_lp[1][mm + 8]);
    }
#pragma unroll
    for (int mt = 0; mt < 2; mt++) {
        const int m = m0 + pm + (mt << 4) + g;
#pragma unroll
        for (int ct = 0; ct < 8; ct++) {
            const int c = pc + (ct << 3) + 2 * t;
            const float4 d = acc[mt][ct];
            const size_t i00 = (((size_t)(b << 8) + c) << 12) + m;
            const size_t i01 = i00 + N_;
            out[i00]     = gam * d.x * il0[mt] + xin[i00];
            out[i01]     = gam * d.y * il0[mt] + xin[i01];
            out[i00 + 8] = gam * d.z * il1[mt] + xin[i00 + 8];
            out[i01 + 8] = gam * d.w * il1[mt] + xin[i01 + 8];
        }
    }
}

// ---------------------------------------------------------------------------
extern "C" void kernel_launch(void* const* d_in, const int* in_sizes, int n_in,
                              void* d_out, int out_size)
{
    const float* x     = (const float*)d_in[0];
    const float* Wq    = (const float*)d_in[1];
    const float* bq    = (const float*)d_in[2];
    const float* Wk    = (const float*)d_in[3];
    const float* bk    = (const float*)d_in[4];
    const float* Wv    = (const float*)d_in[5];
    const float* bv    = (const float*)d_in[6];
    const float* gamma = (const float*)d_in[7];
    float* out = (float*)d_out;

    static bool attr_set = false;
    if (!attr_set) {
        cudaFuncSetAttribute(proj_qkv_kernel,
            cudaFuncAttributeMaxDynamicSharedMemorySize, PQ_SMEM);
        cudaFuncSetAttribute(attn_fused_kernel,
            cudaFuncAttributeMaxDynamicSharedMemorySize, FU_SMEM);
        attr_set = true;
    }

    proj_qkv_kernel<<<dim3(N_ / 64, B_), 256, PQ_SMEM>>>(
        x, Wq, bq, Wk, bk, Wv, bv);                         // g_Qn, g_Km, g_Vh
    attn_fused_kernel<<<dim3(N_ / 64, B_), 256, FU_SMEM>>>(x, gamma, out);
}